// round 11
// baseline (speedup 1.0000x reference)
#include <cuda_runtime.h>
#include <cstdint>

#define T_SEQ 512
#define H 32
#define MAXB 4096
#define GSTEP 16   // xin tile depth (steps per prefetch group)

typedef unsigned long long u64;

// scratch: xin[b][t][i]; +24 rows pad so tile prefetch may overrun.
__device__ float g_xin[((size_t)MAXB * T_SEQ + 24) * H];

__device__ __forceinline__ u64 fma2(u64 a, u64 b, u64 c) {
    u64 d;
    asm("fma.rn.f32x2 %0, %1, %2, %3;" : "=l"(d) : "l"(a), "l"(b), "l"(c));
    return d;
}
__device__ __forceinline__ u64 add2(u64 a, u64 b) {
    u64 d;
    asm("add.rn.f32x2 %0, %1, %2;" : "=l"(d) : "l"(a), "l"(b));
    return d;
}
__device__ __forceinline__ u64 pack2(float lo, float hi) {
    u64 d;
    asm("mov.b64 %0, {%1, %2};" : "=l"(d) : "f"(lo), "f"(hi));
    return d;
}
__device__ __forceinline__ float lo_hi_sum(u64 a) {
    unsigned lo, hi;
    asm("mov.b64 {%0,%1}, %2;" : "=r"(lo), "=r"(hi) : "l"(a));
    return __uint_as_float(lo) + __uint_as_float(hi);
}
__device__ __forceinline__ float tanh_mufu(float x) {
    float y;
    asm("tanh.approx.f32 %0, %1;" : "=f"(y) : "f"(x));
    return y;
}

// ============================================================================
// K1: xin precompute (byte-identical to round 9; ~148us).
// ============================================================================
__global__ __launch_bounds__(128)
void xin_kernel(const float* __restrict__ x,
                const float* __restrict__ W_ih1,
                const float* __restrict__ b_ih1,
                const float* __restrict__ b_hh1)
{
    const int tid  = threadIdx.x;
    const int lane = tid & 31;
    const int wid  = tid >> 5;

    __shared__ __align__(16) float sw[32][36];
    __shared__ __align__(16) float sx[4][2][8 * H];

    #pragma unroll
    for (int idx = tid; idx < H * H; idx += 128) sw[idx >> 5][idx & 31] = W_ih1[idx];
    __syncthreads();

    u64 w[16];
    {
        const u64* wr = (const u64*)&sw[lane][0];
        #pragma unroll
        for (int k = 0; k < 16; k++) w[k] = wr[k];
    }
    const u64 biasp = pack2(b_ih1[lane] + b_hh1[lane], 0.0f);

    const long long base = ((long long)blockIdx.x * 4 + wid) * 64;
    const float* xb = x + base * H;
    float* ob = g_xin + base * H;

    float4 p0 = *(const float4*)(xb + lane * 4);
    float4 p1 = *(const float4*)(xb + 128 + lane * 4);

    #pragma unroll
    for (int g = 0; g < 8; g++) {
        const int buf = g & 1;
        *(float4*)&sx[wid][buf][lane * 4]       = p0;
        *(float4*)&sx[wid][buf][128 + lane * 4] = p1;
        if (g < 7) {
            p0 = *(const float4*)(xb + (g + 1) * 256 + lane * 4);
            p1 = *(const float4*)(xb + (g + 1) * 256 + 128 + lane * 4);
        }
        __syncwarp();

        #pragma unroll
        for (int rr = 0; rr < 8; rr += 2) {
            const ulonglong2* xv0 = (const ulonglong2*)&sx[wid][buf][rr * H];
            const ulonglong2* xv1 = (const ulonglong2*)&sx[wid][buf][(rr + 1) * H];
            u64 a0 = biasp, a1 = 0ull, b0 = biasp, b1 = 0ull;
            #pragma unroll
            for (int m = 0; m < 8; m++) {
                ulonglong2 v0 = xv0[m];
                ulonglong2 v1 = xv1[m];
                a0 = fma2(v0.x, w[2 * m],     a0);
                a1 = fma2(v0.y, w[2 * m + 1], a1);
                b0 = fma2(v1.x, w[2 * m],     b0);
                b1 = fma2(v1.y, w[2 * m + 1], b1);
            }
            ob[(g * 8 + rr)     * H + lane] = lo_hi_sum(add2(a0, a1));
            ob[(g * 8 + rr + 1) * H + lane] = lo_hi_sum(add2(b0, b1));
        }
    }
}

// ============================================================================
// K2: 64 threads per sequence. Warp0 = layer1 recurrence, warp1 = layer2
// (layer-pipelined: at step k warp0 makes h1_{k+1}, warp1 makes h2_k).
// Half-j split inside each warp; handoff via smem ping-pong + __syncthreads.
// Per-thread weights: warp0 16 floats, warp1 32 floats -> ~24 warps/SM.
// ============================================================================
__global__ __launch_bounds__(64, 12)
void rnn_rec2_kernel(const float* __restrict__ W_hh1,
                     const float* __restrict__ W_ih2,
                     const float* __restrict__ W_hh2,
                     const float* __restrict__ b_ih2,
                     const float* __restrict__ b_hh2,
                     const float* __restrict__ W_fc,
                     const float* __restrict__ b_fc,
                     float* __restrict__ out, int Bn)
{
    const int tid  = threadIdx.x;
    const int wid  = tid >> 5;         // 0 = layer1 warp, 1 = layer2 warp
    const int lane = tid & 31;
    const int jh   = lane >> 4;        // j-half this lane reads
    const int u0   = lane & 15;
    const int ufin = u0 + 16 * jh;     // unit this lane finalizes
    const int b    = blockIdx.x;
    if (b >= Bn) return;

    __shared__ __align__(16) float s[2][2 * H];       // [pingpong][h1|h2]
    __shared__ __align__(16) float sx[2][GSTEP][32];  // xin tile [buf][d][i]

    const float* xg = g_xin + (size_t)b * T_SEQ * H;

    // prologue: h1_0 = tanh(xin_0) (xin already contains b1), h2_{-1} = 0
    if (tid < 32) {
        s[1][tid]     = tanh_mufu(xg[tid]);
        s[1][H + tid] = 0.0f;
    }
    // tile group 0: rows t = 1..16 (warp w loads rows 1+8w .. 8+8w)
    {
        const int d0 = wid * 8;
        #pragma unroll
        for (int dd = 0; dd < 8; dd++)
            sx[0][d0 + dd][lane] = xg[(size_t)(1 + d0 + dd) * H + lane];
    }
    __syncthreads();

    const int off = jh * 16;

    if (wid == 0) {
        // ---------------- layer-1 warp ----------------
        u64 wa0[8], wa1[8];    // W_hh1 rows u0, u0+16 (half jh)
        {
            const u64* p1 = (const u64*)(W_hh1 + u0 * H + off);
            const u64* p2 = (const u64*)(W_hh1 + (u0 + 16) * H + off);
            #pragma unroll
            for (int k = 0; k < 8; k++) { wa0[k] = p1[k]; wa1[k] = p2[k]; }
        }

        for (int g = 0; g < T_SEQ / GSTEP; ++g) {
            const int buf = g & 1;
            // prefetch this warp's half of the next tile: rows (g+1)*16+1 .. +8
            {
                const size_t tb = (size_t)(g + 1) * GSTEP + 1;
                #pragma unroll
                for (int dd = 0; dd < 8; dd++)
                    sx[buf ^ 1][dd][lane] = xg[(tb + dd) * H + lane];
            }

            #pragma unroll 2
            for (int kk = 0; kk < GSTEP; ++kk) {
                const int p = kk & 1;
                const ulonglong2* h1v = (const ulonglong2*)&s[p ^ 1][jh * 16];

                u64 a0 = 0ull, a1 = 0ull;
                #pragma unroll
                for (int m = 0; m < 4; m++) {
                    ulonglong2 v = h1v[m];
                    a0 = fma2(v.x, wa0[2 * m],     a0);
                    a0 = fma2(v.y, wa0[2 * m + 1], a0);
                    a1 = fma2(v.x, wa1[2 * m],     a1);
                    a1 = fma2(v.y, wa1[2 * m + 1], a1);
                }
                float sa0 = lo_hi_sum(a0), sa1 = lo_hi_sum(a1);
                float send = jh ? sa0 : sa1;
                float recv = __shfl_xor_sync(0xFFFFFFFFu, send, 16);
                float keep = jh ? sa1 : sa0;

                const float xinv = sx[buf][kk][ufin];   // xin_{k+1}[ufin]
                const float h1n  = tanh_mufu(keep + recv + xinv);

                s[p][ufin] = h1n;
                __syncthreads();
            }
        }
    } else {
        // ---------------- layer-2 warp ----------------
        u64 wc0[8], wc1[8], wd0[8], wd1[8];   // W_ih2, W_hh2 half-rows
        {
            const u64* p1 = (const u64*)(W_ih2 + u0 * H + off);
            const u64* p2 = (const u64*)(W_ih2 + (u0 + 16) * H + off);
            const u64* p3 = (const u64*)(W_hh2 + u0 * H + off);
            const u64* p4 = (const u64*)(W_hh2 + (u0 + 16) * H + off);
            #pragma unroll
            for (int k = 0; k < 8; k++) {
                wc0[k] = p1[k]; wc1[k] = p2[k]; wd0[k] = p3[k]; wd1[k] = p4[k];
            }
        }
        // bias folded into the chain that this lane finalizes
        const u64 c0i = (jh == 0) ? pack2(b_ih2[u0]      + b_hh2[u0],      0.0f) : 0ull;
        const u64 c1i = (jh == 1) ? pack2(b_ih2[u0 + 16] + b_hh2[u0 + 16], 0.0f) : 0ull;

        for (int g = 0; g < T_SEQ / GSTEP; ++g) {
            const int buf = g & 1;
            // prefetch this warp's half of the next tile: rows (g+1)*16+9 .. +16
            {
                const size_t tb = (size_t)(g + 1) * GSTEP + 9;
                #pragma unroll
                for (int dd = 0; dd < 8; dd++)
                    sx[buf ^ 1][8 + dd][lane] = xg[(tb + dd) * H + lane];
            }

            #pragma unroll 2
            for (int kk = 0; kk < GSTEP; ++kk) {
                const int p = kk & 1;
                const ulonglong2* h1v = (const ulonglong2*)&s[p ^ 1][jh * 16];
                const ulonglong2* h2v = (const ulonglong2*)&s[p ^ 1][H + jh * 16];

                u64 c0 = c0i, c1 = c1i;
                #pragma unroll
                for (int m = 0; m < 4; m++) {
                    ulonglong2 v = h1v[m];
                    c0 = fma2(v.x, wc0[2 * m],     c0);
                    c0 = fma2(v.y, wc0[2 * m + 1], c0);
                    c1 = fma2(v.x, wc1[2 * m],     c1);
                    c1 = fma2(v.y, wc1[2 * m + 1], c1);
                }
                #pragma unroll
                for (int m = 0; m < 4; m++) {
                    ulonglong2 v = h2v[m];
                    c0 = fma2(v.x, wd0[2 * m],     c0);
                    c0 = fma2(v.y, wd0[2 * m + 1], c0);
                    c1 = fma2(v.x, wd1[2 * m],     c1);
                    c1 = fma2(v.y, wd1[2 * m + 1], c1);
                }
                float sc0 = lo_hi_sum(c0), sc1 = lo_hi_sum(c1);
                float send = jh ? sc0 : sc1;
                float recv = __shfl_xor_sync(0xFFFFFFFFu, send, 16);
                float keep = jh ? sc1 : sc0;

                const float h2n = tanh_mufu(keep + recv);

                s[p][H + ufin] = h2n;
                __syncthreads();
            }
        }
    }

    // final bar of step 511 (inside both loops) already ordered the last
    // h2 write (to buffer (511)&1 = 1). FC head on warp 0:
    if (tid < 32) {
        float v = s[1][H + tid] * W_fc[tid];
        #pragma unroll
        for (int o = 16; o; o >>= 1) v += __shfl_xor_sync(0xFFFFFFFFu, v, o);
        if (tid == 0) out[b] = v + b_fc[0];
    }
}

extern "C" void kernel_launch(void* const* d_in, const int* in_sizes, int n_in,
                              void* d_out, int out_size)
{
    const float* x     = (const float*)d_in[0];
    const float* W_ih1 = (const float*)d_in[1];
    const float* W_hh1 = (const float*)d_in[2];
    const float* b_ih1 = (const float*)d_in[3];
    const float* b_hh1 = (const float*)d_in[4];
    const float* W_ih2 = (const float*)d_in[5];
    const float* W_hh2 = (const float*)d_in[6];
    const float* b_ih2 = (const float*)d_in[7];
    const float* b_hh2 = (const float*)d_in[8];
    const float* W_fc  = (const float*)d_in[9];
    const float* b_fc  = (const float*)d_in[10];
    float* out = (float*)d_out;

    const int Bn = in_sizes[0] / (T_SEQ * H);

    const int rows = Bn * T_SEQ;
    xin_kernel<<<rows / 256, 128>>>(x, W_ih1, b_ih1, b_hh1);

    // 2 warps per sequence
    rnn_rec2_kernel<<<Bn, 64>>>(
        W_hh1, W_ih2, W_hh2, b_ih2, b_hh2, W_fc, b_fc, out, Bn);
}